// round 5
// baseline (speedup 1.0000x reference)
#include <cuda_runtime.h>
#include <cuda_bf16.h>
#include <cstdint>

#define NUM_CLASSES 32000
#define EMBED_DIM   128
#define N_TOKENS    (64 * 4096)      // 262144
#define MAXK        64               // bucket capacity per class (avg occupancy ~8.2)

// Scratch (device globals; zero-initialized at module load)
__device__ float g_Wt[NUM_CLASSES * EMBED_DIM];        // 16.4 MB: W^T + bias
__device__ int   g_bucket[NUM_CLASSES * MAXK];         // 8.2 MB: token ids per class
__device__ int   g_cursor[NUM_CLASSES];                // per-class counts (reset by kernel B)
__device__ int   g_overflow[N_TOKENS];                 // full-capacity overflow list
__device__ int   g_over_cnt;                           // reset by kernel B

#define T_BLOCKS 1000   // transpose blocks: (NUM_CLASSES/128) * (EMBED_DIM/32)
#define B_BLOCKS 256    // bucket-build blocks: 256 * 256 threads * 4 tokens = 262144
#define C_BLOCKS 4000   // scatter blocks: 4000 * 8 warps = 32000 classes

// ---------------------------------------------------------------------------
// Kernel A: [blocks 0..999] transpose+bias  ||  [blocks 1000..1255] bucket build
// ---------------------------------------------------------------------------
__global__ void prep_kernel(const float* __restrict__ W,
                            const float* __restrict__ b,
                            const int*   __restrict__ x) {
    if (blockIdx.x < T_BLOCKS) {
        // ---- transpose + bias: tile = 32 d-rows x 128 classes ----
        __shared__ float smemT[128][33];
        int blk = blockIdx.x;
        int c0 = (blk % 250) * 128;
        int d0 = (blk / 250) * 32;

        int t    = threadIdx.x;          // 0..255
        int lane = t & 31;
        int warp = t >> 5;

        const float4* __restrict__ W4 = (const float4*)W;
        int cx = t & 31;
        #pragma unroll
        for (int i = 0; i < 4; i++) {
            int row = (t >> 5) + i * 8;
            float4 v = W4[(size_t)(d0 + row) * (NUM_CLASSES / 4) + (c0 >> 2) + cx];
            smemT[4 * cx + 0][row] = v.x;
            smemT[4 * cx + 1][row] = v.y;
            smemT[4 * cx + 2][row] = v.z;
            smemT[4 * cx + 3][row] = v.w;
        }
        __syncthreads();

        float bias = b[d0 + lane];
        #pragma unroll
        for (int i = 0; i < 16; i++) {
            int c = warp + i * 8;
            g_Wt[(size_t)(c0 + c) * EMBED_DIM + (d0 + lane)] = smemT[c][lane] + bias;
        }
    } else {
        // ---- bucket build: 4 tokens per thread via int4 load ----
        int blk = blockIdx.x - T_BLOCKS;
        int tid = blk * blockDim.x + threadIdx.x;   // 0..65535
        int4 tok4 = ((const int4*)x)[tid];
        int base = tid * 4;

        #pragma unroll
        for (int i = 0; i < 4; i++) {
            int c = (i == 0) ? tok4.x : (i == 1) ? tok4.y : (i == 2) ? tok4.z : tok4.w;
            c = min(max(c, 0), NUM_CLASSES - 1);
            int slot = atomicAdd(&g_cursor[c], 1);
            if (slot < MAXK) {
                g_bucket[c * MAXK + slot] = base + i;
            } else {
                int os = atomicAdd(&g_over_cnt, 1);
                g_overflow[os] = base + i;          // capacity = N_TOKENS: never lost
            }
        }
    }
}

// ---------------------------------------------------------------------------
// Kernel B: one warp per class. Read row once (L2), broadcast-write to all
// its tokens. Block C_BLOCKS handles the overflow list. Resets cursors for
// the next graph replay.
// ---------------------------------------------------------------------------
__global__ void scatter_kernel(const int* __restrict__ x,
                               float4* __restrict__ out) {
    int lane = threadIdx.x & 31;
    int warp = threadIdx.x >> 5;
    const float4* __restrict__ Wt4 = (const float4*)g_Wt;

    if (blockIdx.x < C_BLOCKS) {
        int c = blockIdx.x * 8 + warp;               // class id, < 32000

        // issue row load early (mostly L2 hit: table written last kernel)
        float4 row = __ldcg(&Wt4[(size_t)c * 32 + lane]);

        int k  = g_cursor[c];
        int kc = min(k, MAXK);

        for (int bse = 0; bse < kc; bse += 32) {
            int nb = min(32, kc - bse);
            int myt = (bse + lane < kc) ? g_bucket[c * MAXK + bse + lane] : 0;
            for (int i = 0; i < nb; i++) {
                int tok = __shfl_sync(0xffffffffu, myt, i);
                __stcs(&out[(size_t)tok * 32 + lane], row);
            }
        }
        if (lane == 0) g_cursor[c] = 0;              // reset for next replay
    } else {
        // ---- overflow drain: direct gather per token (normally empty) ----
        int n_over = g_over_cnt;
        // 8 warps grid-stride over the overflow list
        for (int i = warp; i < n_over; i += 8) {
            int tok = g_overflow[i];
            int c = min(max(x[tok], 0), NUM_CLASSES - 1);
            float4 row = __ldcg(&Wt4[(size_t)c * 32 + lane]);
            __stcs(&out[(size_t)tok * 32 + lane], row);
        }
        __syncthreads();
        if (threadIdx.x == 0) g_over_cnt = 0;        // reset for next replay
    }
}

extern "C" void kernel_launch(void* const* d_in, const int* in_sizes, int n_in,
                              void* d_out, int out_size) {
    const int*   x = (const int*)d_in[0];        // (64, 4096) int32
    const float* W = (const float*)d_in[1];      // (128, 32000) fp32
    const float* b = (const float*)d_in[2];      // (128,) fp32
    float4*    out = (float4*)d_out;             // (64, 4096, 128) fp32

    prep_kernel<<<T_BLOCKS + B_BLOCKS, 256>>>(W, b, x);
    scatter_kernel<<<C_BLOCKS + 1, 256>>>(x, out);
}